// round 2
// baseline (speedup 1.0000x reference)
#include <cuda_runtime.h>

// EvroModel: x[131072,256] -> relu(x@w1+b1)[.,64] -> tanh(@w2+b2)[.,16] -> @w3+b3 [.,4]
// -> softmax over the ENTIRE flattened tensor.
//
// Round 2: packed dual-fp32 FMA (fma.rn.f32x2 -> SASS FFMA2), halving the
// FFMA instruction count of layer 1 (the dominant cost) and layer 2.
// Arithmetic is still IEEE fp32 FMA per lane -> accuracy unchanged.

#define B_ROWS 131072
#define TPB 256
#define NBLK (B_ROWS / TPB)   // 512

__device__ float g_partials[NBLK];
__device__ float g_inv_sum;

#define SM_FLOATS 17556

typedef unsigned long long u64;

__device__ __forceinline__ u64 pack2(float a, float b) {
    u64 r;
    asm("mov.b64 %0, {%1, %2};" : "=l"(r) : "f"(a), "f"(b));
    return r;
}
__device__ __forceinline__ void unpack2(u64 v, float& a, float& b) {
    asm("mov.b64 {%0, %1}, %2;" : "=f"(a), "=f"(b) : "l"(v));
}
__device__ __forceinline__ u64 fma2(u64 a, u64 b, u64 c) {
    u64 d;
    asm("fma.rn.f32x2 %0, %1, %2, %3;" : "=l"(d) : "l"(a), "l"(b), "l"(c));
    return d;
}

__global__ __launch_bounds__(TPB, 2)
void mlp_kernel(const float* __restrict__ x,
                const float* __restrict__ w1, const float* __restrict__ b1,
                const float* __restrict__ w2, const float* __restrict__ b2,
                const float* __restrict__ w3, const float* __restrict__ b3,
                float* __restrict__ out)
{
    extern __shared__ float sm[];
    float* sw1 = sm;            // 16384 floats (256x64)
    float* sw2 = sm + 16384;    // 1024  (64x16)
    float* sb1 = sm + 17408;    // 64
    float* sb2 = sm + 17472;    // 16
    float* sw3 = sm + 17488;    // 64 (16x4)
    float* sb3 = sm + 17552;    // 4
    __shared__ float red[TPB];

    const int tid = threadIdx.x;

    // Stage weights cooperatively.
    {
        const float4* w1v = (const float4*)w1;
        float4* sw1v = (float4*)sw1;
        #pragma unroll 4
        for (int i = tid; i < 4096; i += TPB) sw1v[i] = w1v[i];
        const float4* w2v = (const float4*)w2;
        float4* sw2v = (float4*)sw2;
        for (int i = tid; i < 256; i += TPB) sw2v[i] = w2v[i];
        if (tid < 64) sb1[tid] = b1[tid];
        if (tid < 16) sb2[tid] = b2[tid];
        if (tid < 64) sw3[tid] = w3[tid];
        if (tid < 4)  sb3[tid] = b3[tid];
    }
    __syncthreads();

    const int row = blockIdx.x * TPB + tid;
    const float4* xr = (const float4*)(x + (size_t)row * 256);

    // ---- layer 1: 32 packed accumulators (64 outputs) ----
    u64 acc2[32];
    #pragma unroll
    for (int j = 0; j < 32; j++) acc2[j] = pack2(sb1[2 * j], sb1[2 * j + 1]);

    float4 xv = __ldg(&xr[0]);
    #pragma unroll 1
    for (int k4 = 0; k4 < 64; k4++) {
        float4 xn = __ldg(&xr[(k4 + 1) & 63]);   // prefetch (wrap harmless)
        const u64* wr0 = (const u64*)&sw1[(k4 * 4 + 0) * 64];
        const u64* wr1 = (const u64*)&sw1[(k4 * 4 + 1) * 64];
        const u64* wr2 = (const u64*)&sw1[(k4 * 4 + 2) * 64];
        const u64* wr3 = (const u64*)&sw1[(k4 * 4 + 3) * 64];
        const u64 xx = pack2(xv.x, xv.x);
        const u64 xy = pack2(xv.y, xv.y);
        const u64 xz = pack2(xv.z, xv.z);
        const u64 xw = pack2(xv.w, xv.w);
        #pragma unroll
        for (int j = 0; j < 32; j++) acc2[j] = fma2(xx, wr0[j], acc2[j]);
        #pragma unroll
        for (int j = 0; j < 32; j++) acc2[j] = fma2(xy, wr1[j], acc2[j]);
        #pragma unroll
        for (int j = 0; j < 32; j++) acc2[j] = fma2(xz, wr2[j], acc2[j]);
        #pragma unroll
        for (int j = 0; j < 32; j++) acc2[j] = fma2(xw, wr3[j], acc2[j]);
        xv = xn;
    }

    // ---- layer 2: h2[16] = tanh(b2 + relu(h1) @ w2), packed as 8 f32x2 ----
    u64 h2p[8];
    #pragma unroll
    for (int j = 0; j < 8; j++) h2p[j] = pack2(sb2[2 * j], sb2[2 * j + 1]);

    #pragma unroll
    for (int i2 = 0; i2 < 32; i2++) {
        float a, b;
        unpack2(acc2[i2], a, b);
        float ha = fmaxf(a, 0.0f);
        float hb = fmaxf(b, 0.0f);
        const u64* wra = (const u64*)&sw2[(2 * i2) * 16];
        const u64* wrb = (const u64*)&sw2[(2 * i2 + 1) * 16];
        const u64 haa = pack2(ha, ha);
        const u64 hbb = pack2(hb, hb);
        #pragma unroll
        for (int j = 0; j < 8; j++) h2p[j] = fma2(haa, wra[j], h2p[j]);
        #pragma unroll
        for (int j = 0; j < 8; j++) h2p[j] = fma2(hbb, wrb[j], h2p[j]);
    }

    float h2[16];
    #pragma unroll
    for (int j = 0; j < 8; j++) unpack2(h2p[j], h2[2 * j], h2[2 * j + 1]);
    #pragma unroll
    for (int j = 0; j < 16; j++) h2[j] = tanhf(h2[j]);

    // ---- layer 3: logits[4] ----
    float lg[4];
    #pragma unroll
    for (int j = 0; j < 4; j++) lg[j] = sb3[j];
    #pragma unroll
    for (int i = 0; i < 16; i++) {
        float h = h2[i];
        const float* wr = &sw3[i * 4];
        #pragma unroll
        for (int j = 0; j < 4; j++) lg[j] = fmaf(h, wr[j], lg[j]);
    }

    // exp (logits bounded ~|20| -> no max subtraction needed)
    float e0 = __expf(lg[0]);
    float e1 = __expf(lg[1]);
    float e2 = __expf(lg[2]);
    float e3 = __expf(lg[3]);

    float4 ev; ev.x = e0; ev.y = e1; ev.z = e2; ev.w = e3;
    ((float4*)out)[row] = ev;

    // deterministic block partial sum
    red[tid] = (e0 + e1) + (e2 + e3);
    __syncthreads();
    #pragma unroll
    for (int off = TPB / 2; off > 0; off >>= 1) {
        if (tid < off) red[tid] += red[tid + off];
        __syncthreads();
    }
    if (tid == 0) g_partials[blockIdx.x] = red[0];
}

__global__ void reduce_kernel()
{
    __shared__ float red[NBLK];
    const int tid = threadIdx.x;
    red[tid] = g_partials[tid];
    __syncthreads();
    #pragma unroll
    for (int off = NBLK / 2; off > 0; off >>= 1) {
        if (tid < off) red[tid] += red[tid + off];
        __syncthreads();
    }
    if (tid == 0) g_inv_sum = 1.0f / red[0];
}

__global__ void scale_kernel(float* __restrict__ out)
{
    const int i = blockIdx.x * blockDim.x + threadIdx.x;  // one float4 per thread
    const float inv = g_inv_sum;
    float4 v = ((float4*)out)[i];
    v.x *= inv; v.y *= inv; v.z *= inv; v.w *= inv;
    ((float4*)out)[i] = v;
}

extern "C" void kernel_launch(void* const* d_in, const int* in_sizes, int n_in,
                              void* d_out, int out_size)
{
    const float* x  = (const float*)d_in[0];
    const float* w1 = (const float*)d_in[1];
    const float* b1 = (const float*)d_in[2];
    const float* w2 = (const float*)d_in[3];
    const float* b2 = (const float*)d_in[4];
    const float* w3 = (const float*)d_in[5];
    const float* b3 = (const float*)d_in[6];
    float* out = (float*)d_out;

    const size_t smem = SM_FLOATS * sizeof(float);
    cudaFuncSetAttribute(mlp_kernel, cudaFuncAttributeMaxDynamicSharedMemorySize, (int)smem);

    mlp_kernel<<<NBLK, TPB, smem>>>(x, w1, b1, w2, b2, w3, b3, out);
    reduce_kernel<<<1, NBLK>>>();
    scale_kernel<<<(B_ROWS * 4) / (4 * 256), 256>>>(out);
}

// round 4
// speedup vs baseline: 1.3177x; 1.3177x over previous
#include <cuda_runtime.h>
#include <cstdint>

// EvroModel: x[131072,256] -> relu(x@w1+b1)[.,64] -> tanh(@w2+b2)[.,16] -> @w3+b3 [.,4]
// -> softmax over the ENTIRE flattened tensor.
//
// Round 4: layer 1 on tensor cores via warp-level mma.sync.m16n8k8 TF32
// (plain PTX, works at compute_103 — tcgen05 is unreachable in this toolchain).
// Accuracy: 3xTF32 split (xh+xl, wh+wl; accumulate xh*wh + xh*wl + xl*wh in fp32).
// Layers 2/3 + global softmax remain the proven fp32 tail.

#define B_ROWS   131072
#define ROWS_CTA 128
#define NBLK     (B_ROWS / ROWS_CTA)   // 1024
#define TPB      128
#define KDIM     256
#define W_PITCH  72                    // conflict-free B-frag LDS
#define H1_PITCH 68

// dynamic smem layout in floats
#define WH_OFF   0                     // 256 x 72
#define WL_OFF   18432                 // 256 x 72
#define H1_OFF   36864                 // 128 x 68
#define W2_OFF   45568                 // 64 x 16
#define B1_OFF   46592                 // 64
#define B2_OFF   46656                 // 16
#define W3_OFF   46672                 // 16 x 4
#define B3_OFF   46736                 // 4
#define RED_OFF  46740                 // 128
#define SM_FLOATS 46868

__device__ float g_partials[NBLK];
__device__ float g_inv_sum;

__device__ __forceinline__ uint32_t f2tf32(float v) {
    uint32_t u;
    asm("cvt.rna.tf32.f32 %0, %1;" : "=r"(u) : "f"(v));
    return u;
}

__device__ __forceinline__ void mma_tf32(float c[4], const uint32_t a[4],
                                         uint32_t b0, uint32_t b1) {
    asm("mma.sync.aligned.m16n8k8.row.col.f32.tf32.tf32.f32 "
        "{%0,%1,%2,%3}, {%4,%5,%6,%7}, {%8,%9}, {%0,%1,%2,%3};"
        : "+f"(c[0]), "+f"(c[1]), "+f"(c[2]), "+f"(c[3])
        : "r"(a[0]), "r"(a[1]), "r"(a[2]), "r"(a[3]), "r"(b0), "r"(b1));
}

__global__ __launch_bounds__(TPB, 1)
void mlp_kernel(const float* __restrict__ x,
                const float* __restrict__ w1, const float* __restrict__ b1,
                const float* __restrict__ w2, const float* __restrict__ b2,
                const float* __restrict__ w3, const float* __restrict__ b3,
                float* __restrict__ out)
{
    extern __shared__ float sm[];
    float*    swh  = sm + WH_OFF;
    float*    swl  = sm + WL_OFF;
    uint32_t* swhu = (uint32_t*)swh;
    uint32_t* swlu = (uint32_t*)swl;
    float*    sh1  = sm + H1_OFF;

    const int tid = threadIdx.x;
    const int wid = tid >> 5;
    const int lane = tid & 31;
    const int g = lane >> 2;       // group id 0..7
    const int tig = lane & 3;      // thread in group 0..3

    // ---- stage w1 split into tf32 hi/lo (pitch 72) + tail weights ----
    for (int e = tid; e < 16384; e += TPB) {
        int k = e >> 6, n = e & 63;
        float v = w1[e];
        uint32_t hi = f2tf32(v);
        uint32_t lo = f2tf32(v - __uint_as_float(hi));
        swhu[k * W_PITCH + n] = hi;
        swlu[k * W_PITCH + n] = lo;
    }
    {
        float* sw2 = sm + W2_OFF;
        for (int i = tid; i < 1024; i += TPB) sw2[i] = w2[i];
        if (tid < 64) sm[B1_OFF + tid] = b1[tid];
        if (tid < 16) sm[B2_OFF + tid] = b2[tid];
        if (tid < 64) sm[W3_OFF + tid] = w3[tid];
        if (tid < 4)  sm[B3_OFF + tid] = b3[tid];
    }
    __syncthreads();

    // ---- layer-1 GEMM: this warp computes rows [wid*32, wid*32+32), all 64 cols ----
    // per m-tile (16 rows): A frag a0..a3 at rows g/g+8, cols tig/tig+4
    const float* xb = x + ((size_t)blockIdx.x * ROWS_CTA + wid * 32 + g) * KDIM + tig;

    float c[2][8][4];
    #pragma unroll
    for (int mt = 0; mt < 2; mt++)
        #pragma unroll
        for (int nt = 0; nt < 8; nt++)
            #pragma unroll
            for (int r = 0; r < 4; r++) c[mt][nt][r] = 0.0f;

    float ra[2][4];
    #pragma unroll
    for (int mt = 0; mt < 2; mt++) {
        const float* q = xb + mt * (16 * KDIM);
        ra[mt][0] = __ldg(q);
        ra[mt][1] = __ldg(q + 8 * KDIM);
        ra[mt][2] = __ldg(q + 4);
        ra[mt][3] = __ldg(q + 8 * KDIM + 4);
    }

    #pragma unroll 1
    for (int kt = 0; kt < 32; kt++) {
        // prefetch next k-tile's A
        float rb[2][4];
        if (kt < 31) {
            #pragma unroll
            for (int mt = 0; mt < 2; mt++) {
                const float* q = xb + mt * (16 * KDIM) + (kt + 1) * 8;
                rb[mt][0] = __ldg(q);
                rb[mt][1] = __ldg(q + 8 * KDIM);
                rb[mt][2] = __ldg(q + 4);
                rb[mt][3] = __ldg(q + 8 * KDIM + 4);
            }
        }

        // split current A into tf32 hi/lo
        uint32_t ah[2][4], al[2][4];
        #pragma unroll
        for (int mt = 0; mt < 2; mt++)
            #pragma unroll
            for (int i = 0; i < 4; i++) {
                uint32_t hi = f2tf32(ra[mt][i]);
                ah[mt][i] = hi;
                al[mt][i] = f2tf32(ra[mt][i] - __uint_as_float(hi));
            }

        const int kr0 = (kt * 8 + tig) * W_PITCH + g;
        const int kr1 = (kt * 8 + tig + 4) * W_PITCH + g;
        #pragma unroll
        for (int nt = 0; nt < 8; nt++) {
            uint32_t bh0 = swhu[kr0 + nt * 8];
            uint32_t bh1 = swhu[kr1 + nt * 8];
            uint32_t bl0 = swlu[kr0 + nt * 8];
            uint32_t bl1 = swlu[kr1 + nt * 8];
            #pragma unroll
            for (int mt = 0; mt < 2; mt++) {
                mma_tf32(c[mt][nt], ah[mt], bh0, bh1);
                mma_tf32(c[mt][nt], ah[mt], bl0, bl1);
                mma_tf32(c[mt][nt], al[mt], bh0, bh1);
            }
        }

        #pragma unroll
        for (int mt = 0; mt < 2; mt++)
            #pragma unroll
            for (int i = 0; i < 4; i++) ra[mt][i] = rb[mt][i];
    }

    // ---- write C frags to h1 smem (pitch 68) ----
    #pragma unroll
    for (int mt = 0; mt < 2; mt++) {
        int row0 = wid * 32 + mt * 16 + g;
        #pragma unroll
        for (int nt = 0; nt < 8; nt++) {
            int col = nt * 8 + tig * 2;
            float2 v0; v0.x = c[mt][nt][0]; v0.y = c[mt][nt][1];
            float2 v1; v1.x = c[mt][nt][2]; v1.y = c[mt][nt][3];
            *(float2*)&sh1[row0 * H1_PITCH + col] = v0;
            *(float2*)&sh1[(row0 + 8) * H1_PITCH + col] = v1;
        }
    }
    __syncthreads();

    // ---- per-thread fp32 tail: row = tid ----
    const float* sb1 = sm + B1_OFF;
    const float* sw2 = sm + W2_OFF;
    const float* sb2 = sm + B2_OFF;
    const float* sw3 = sm + W3_OFF;
    const float* sb3 = sm + B3_OFF;
    const float* hrow = &sh1[tid * H1_PITCH];

    float h2[16];
    #pragma unroll
    for (int j = 0; j < 16; j++) h2[j] = sb2[j];
    #pragma unroll
    for (int i4 = 0; i4 < 16; i4++) {
        float4 hv = *(const float4*)&hrow[i4 * 4];
        float h0 = fmaxf(hv.x + sb1[i4 * 4 + 0], 0.0f);
        float h1v = fmaxf(hv.y + sb1[i4 * 4 + 1], 0.0f);
        float h2v = fmaxf(hv.z + sb1[i4 * 4 + 2], 0.0f);
        float h3 = fmaxf(hv.w + sb1[i4 * 4 + 3], 0.0f);
        const float* wr0 = &sw2[(i4 * 4 + 0) * 16];
        const float* wr1 = &sw2[(i4 * 4 + 1) * 16];
        const float* wr2 = &sw2[(i4 * 4 + 2) * 16];
        const float* wr3 = &sw2[(i4 * 4 + 3) * 16];
        #pragma unroll
        for (int j = 0; j < 16; j++) {
            float t = fmaf(h0, wr0[j], h2[j]);
            t = fmaf(h1v, wr1[j], t);
            t = fmaf(h2v, wr2[j], t);
            h2[j] = fmaf(h3, wr3[j], t);
        }
    }
    #pragma unroll
    for (int j = 0; j < 16; j++) h2[j] = tanhf(h2[j]);

    float lg[4];
    #pragma unroll
    for (int j = 0; j < 4; j++) lg[j] = sb3[j];
    #pragma unroll
    for (int i = 0; i < 16; i++) {
        float h = h2[i];
        const float* wr = &sw3[i * 4];
        #pragma unroll
        for (int j = 0; j < 4; j++) lg[j] = fmaf(h, wr[j], lg[j]);
    }

    float e0 = __expf(lg[0]);
    float e1 = __expf(lg[1]);
    float e2 = __expf(lg[2]);
    float e3 = __expf(lg[3]);

    const size_t row = (size_t)blockIdx.x * ROWS_CTA + tid;
    float4 ev; ev.x = e0; ev.y = e1; ev.z = e2; ev.w = e3;
    ((float4*)out)[row] = ev;

    // deterministic block partial sum
    float* red = sm + RED_OFF;
    red[tid] = (e0 + e1) + (e2 + e3);
    __syncthreads();
    #pragma unroll
    for (int off = TPB / 2; off > 0; off >>= 1) {
        if (tid < off) red[tid] += red[tid + off];
        __syncthreads();
    }
    if (tid == 0) g_partials[blockIdx.x] = red[0];
}

__global__ void reduce_kernel()
{
    __shared__ float red[NBLK];
    const int tid = threadIdx.x;
    red[tid] = g_partials[tid];
    __syncthreads();
    #pragma unroll
    for (int off = NBLK / 2; off > 0; off >>= 1) {
        if (tid < off) red[tid] += red[tid + off];
        __syncthreads();
    }
    if (tid == 0) g_inv_sum = 1.0f / red[0];
}

__global__ void scale_kernel(float* __restrict__ out)
{
    const int i = blockIdx.x * blockDim.x + threadIdx.x;  // one float4 per thread
    const float inv = g_inv_sum;
    float4 v = ((float4*)out)[i];
    v.x *= inv; v.y *= inv; v.z *= inv; v.w *= inv;
    ((float4*)out)[i] = v;
}

extern "C" void kernel_launch(void* const* d_in, const int* in_sizes, int n_in,
                              void* d_out, int out_size)
{
    const float* x  = (const float*)d_in[0];
    const float* w1 = (const float*)d_in[1];
    const float* b1 = (const float*)d_in[2];
    const float* w2 = (const float*)d_in[3];
    const float* b2 = (const float*)d_in[4];
    const float* w3 = (const float*)d_in[5];
    const float* b3 = (const float*)d_in[6];
    float* out = (float*)d_out;

    const size_t smem = SM_FLOATS * sizeof(float);
    cudaFuncSetAttribute(mlp_kernel, cudaFuncAttributeMaxDynamicSharedMemorySize, (int)smem);

    mlp_kernel<<<NBLK, TPB, smem>>>(x, w1, b1, w2, b2, w3, b3, out);
    reduce_kernel<<<1, NBLK>>>();
    scale_kernel<<<(B_ROWS * 4) / (4 * 256), 256>>>(out);
}

// round 5
// speedup vs baseline: 2.3426x; 1.7778x over previous
#include <cuda_runtime.h>
#include <cstdint>

// EvroModel: x[131072,256] -> relu(x@w1+b1)[.,64] -> tanh(@w2+b2)[.,16] -> @w3+b3 [.,4]
// -> softmax over the ENTIRE flattened tensor.
//
// Round 5: same 3xTF32 mma.sync GEMM as Round 4, but TPB 128->512 (16 warps/CTA,
// occ 6%->25%) to hide HMMA/LDS latency; h1 staging aliased over the dead
// w1-split region so SMEM still fits in one CTA/SM.

#define B_ROWS   131072
#define ROWS_CTA 512
#define NBLK     (B_ROWS / ROWS_CTA)   // 256
#define TPB      512
#define KDIM     256
#define W_PITCH  72                    // conflict-free B-frag LDS
#define H1_PITCH 68

// dynamic smem layout in floats
#define WH_OFF   0                     // 256 x 72
#define WL_OFF   18432                 // 256 x 72
#define H1_OFF   0                     // ALIAS: 512 x 68 over WH/WL after GEMM
#define W2_OFF   36864                 // 64 x 16
#define B1_OFF   37888                 // 64
#define B2_OFF   37952                 // 16
#define W3_OFF   37968                 // 16 x 4
#define B3_OFF   38032                 // 4
#define RED_OFF  38036                 // 512
#define SM_FLOATS 38548

__device__ float g_partials[NBLK];
__device__ float g_inv_sum;

__device__ __forceinline__ uint32_t f2tf32(float v) {
    uint32_t u;
    asm("cvt.rna.tf32.f32 %0, %1;" : "=r"(u) : "f"(v));
    return u;
}

__device__ __forceinline__ void mma_tf32(float c[4], const uint32_t a[4],
                                         uint32_t b0, uint32_t b1) {
    asm("mma.sync.aligned.m16n8k8.row.col.f32.tf32.tf32.f32 "
        "{%0,%1,%2,%3}, {%4,%5,%6,%7}, {%8,%9}, {%0,%1,%2,%3};"
        : "+f"(c[0]), "+f"(c[1]), "+f"(c[2]), "+f"(c[3])
        : "r"(a[0]), "r"(a[1]), "r"(a[2]), "r"(a[3]), "r"(b0), "r"(b1));
}

__global__ __launch_bounds__(TPB, 1)
void mlp_kernel(const float* __restrict__ x,
                const float* __restrict__ w1, const float* __restrict__ b1,
                const float* __restrict__ w2, const float* __restrict__ b2,
                const float* __restrict__ w3, const float* __restrict__ b3,
                float* __restrict__ out)
{
    extern __shared__ float sm[];
    uint32_t* swhu = (uint32_t*)(sm + WH_OFF);
    uint32_t* swlu = (uint32_t*)(sm + WL_OFF);
    float*    sh1  = sm + H1_OFF;    // aliases WH/WL after the GEMM

    const int tid = threadIdx.x;
    const int wid = tid >> 5;
    const int lane = tid & 31;
    const int g = lane >> 2;       // group id 0..7
    const int tig = lane & 3;      // thread in group 0..3

    // ---- stage w1 split into tf32 hi/lo (pitch 72) + tail weights ----
    for (int e = tid; e < 16384; e += TPB) {
        int k = e >> 6, n = e & 63;
        float v = w1[e];
        uint32_t hi = f2tf32(v);
        uint32_t lo = f2tf32(v - __uint_as_float(hi));
        swhu[k * W_PITCH + n] = hi;
        swlu[k * W_PITCH + n] = lo;
    }
    {
        float* sw2 = sm + W2_OFF;
        for (int i = tid; i < 1024; i += TPB) sw2[i] = w2[i];
        if (tid < 64) sm[B1_OFF + tid] = b1[tid];
        if (tid < 16) sm[B2_OFF + tid] = b2[tid];
        if (tid < 64) sm[W3_OFF + tid] = w3[tid];
        if (tid < 4)  sm[B3_OFF + tid] = b3[tid];
    }
    __syncthreads();

    // ---- layer-1 GEMM: this warp computes rows [wid*32, wid*32+32), all 64 cols ----
    const float* xb = x + ((size_t)blockIdx.x * ROWS_CTA + wid * 32 + g) * KDIM + tig;

    float c[2][8][4];
    #pragma unroll
    for (int mt = 0; mt < 2; mt++)
        #pragma unroll
        for (int nt = 0; nt < 8; nt++)
            #pragma unroll
            for (int r = 0; r < 4; r++) c[mt][nt][r] = 0.0f;

    float ra[2][4];
    #pragma unroll
    for (int mt = 0; mt < 2; mt++) {
        const float* q = xb + mt * (16 * KDIM);
        ra[mt][0] = __ldg(q);
        ra[mt][1] = __ldg(q + 8 * KDIM);
        ra[mt][2] = __ldg(q + 4);
        ra[mt][3] = __ldg(q + 8 * KDIM + 4);
    }

    #pragma unroll 1
    for (int kt = 0; kt < 32; kt++) {
        // prefetch next k-tile's A
        float rb[2][4];
        if (kt < 31) {
            #pragma unroll
            for (int mt = 0; mt < 2; mt++) {
                const float* q = xb + mt * (16 * KDIM) + (kt + 1) * 8;
                rb[mt][0] = __ldg(q);
                rb[mt][1] = __ldg(q + 8 * KDIM);
                rb[mt][2] = __ldg(q + 4);
                rb[mt][3] = __ldg(q + 8 * KDIM + 4);
            }
        }

        // split current A into tf32 hi/lo
        uint32_t ah[2][4], al[2][4];
        #pragma unroll
        for (int mt = 0; mt < 2; mt++)
            #pragma unroll
            for (int i = 0; i < 4; i++) {
                uint32_t hi = f2tf32(ra[mt][i]);
                ah[mt][i] = hi;
                al[mt][i] = f2tf32(ra[mt][i] - __uint_as_float(hi));
            }

        const int kr0 = (kt * 8 + tig) * W_PITCH + g;
        const int kr1 = (kt * 8 + tig + 4) * W_PITCH + g;
        #pragma unroll
        for (int nt = 0; nt < 8; nt++) {
            uint32_t bh0 = swhu[kr0 + nt * 8];
            uint32_t bh1 = swhu[kr1 + nt * 8];
            uint32_t bl0 = swlu[kr0 + nt * 8];
            uint32_t bl1 = swlu[kr1 + nt * 8];
            #pragma unroll
            for (int mt = 0; mt < 2; mt++) {
                mma_tf32(c[mt][nt], ah[mt], bh0, bh1);
                mma_tf32(c[mt][nt], ah[mt], bl0, bl1);
                mma_tf32(c[mt][nt], al[mt], bh0, bh1);
            }
        }

        #pragma unroll
        for (int mt = 0; mt < 2; mt++)
            #pragma unroll
            for (int i = 0; i < 4; i++) ra[mt][i] = rb[mt][i];
    }

    // ---- all warps done reading w1 smem; alias it with h1 and write C frags ----
    __syncthreads();
    #pragma unroll
    for (int mt = 0; mt < 2; mt++) {
        int row0 = wid * 32 + mt * 16 + g;
        #pragma unroll
        for (int nt = 0; nt < 8; nt++) {
            int col = nt * 8 + tig * 2;
            float2 v0; v0.x = c[mt][nt][0]; v0.y = c[mt][nt][1];
            float2 v1; v1.x = c[mt][nt][2]; v1.y = c[mt][nt][3];
            *(float2*)&sh1[row0 * H1_PITCH + col] = v0;
            *(float2*)&sh1[(row0 + 8) * H1_PITCH + col] = v1;
        }
    }
    __syncthreads();

    // ---- per-thread fp32 tail: row = tid ----
    const float* sb1 = sm + B1_OFF;
    const float* sw2 = sm + W2_OFF;
    const float* sb2 = sm + B2_OFF;
    const float* sw3 = sm + W3_OFF;
    const float* sb3 = sm + B3_OFF;
    const float* hrow = &sh1[tid * H1_PITCH];

    float h2[16];
    #pragma unroll
    for (int j = 0; j < 16; j++) h2[j] = sb2[j];
    #pragma unroll
    for (int i4 = 0; i4 < 16; i4++) {
        float4 hv = *(const float4*)&hrow[i4 * 4];
        float h0 = fmaxf(hv.x + sb1[i4 * 4 + 0], 0.0f);
        float h1v = fmaxf(hv.y + sb1[i4 * 4 + 1], 0.0f);
        float h2v = fmaxf(hv.z + sb1[i4 * 4 + 2], 0.0f);
        float h3 = fmaxf(hv.w + sb1[i4 * 4 + 3], 0.0f);
        const float* wr0 = &sw2[(i4 * 4 + 0) * 16];
        const float* wr1 = &sw2[(i4 * 4 + 1) * 16];
        const float* wr2 = &sw2[(i4 * 4 + 2) * 16];
        const float* wr3 = &sw2[(i4 * 4 + 3) * 16];
        #pragma unroll
        for (int j = 0; j < 16; j++) {
            float t = fmaf(h0, wr0[j], h2[j]);
            t = fmaf(h1v, wr1[j], t);
            t = fmaf(h2v, wr2[j], t);
            h2[j] = fmaf(h3, wr3[j], t);
        }
    }
    #pragma unroll
    for (int j = 0; j < 16; j++) h2[j] = tanhf(h2[j]);

    float lg[4];
    #pragma unroll
    for (int j = 0; j < 4; j++) lg[j] = sb3[j];
    #pragma unroll
    for (int i = 0; i < 16; i++) {
        float h = h2[i];
        const float* wr = &sw3[i * 4];
        #pragma unroll
        for (int j = 0; j < 4; j++) lg[j] = fmaf(h, wr[j], lg[j]);
    }

    float e0 = __expf(lg[0]);
    float e1 = __expf(lg[1]);
    float e2 = __expf(lg[2]);
    float e3 = __expf(lg[3]);

    const size_t row = (size_t)blockIdx.x * ROWS_CTA + tid;
    float4 ev; ev.x = e0; ev.y = e1; ev.z = e2; ev.w = e3;
    ((float4*)out)[row] = ev;

    // deterministic block partial sum
    float* red = sm + RED_OFF;
    red[tid] = (e0 + e1) + (e2 + e3);
    __syncthreads();
    #pragma unroll
    for (int off = TPB / 2; off > 0; off >>= 1) {
        if (tid < off) red[tid] += red[tid + off];
        __syncthreads();
    }
    if (tid == 0) g_partials[blockIdx.x] = red[0];
}

__global__ void reduce_kernel()
{
    __shared__ float red[NBLK];
    const int tid = threadIdx.x;
    red[tid] = g_partials[tid];
    __syncthreads();
    #pragma unroll
    for (int off = NBLK / 2; off > 0; off >>= 1) {
        if (tid < off) red[tid] += red[tid + off];
        __syncthreads();
    }
    if (tid == 0) g_inv_sum = 1.0f / red[0];
}

__global__ void scale_kernel(float* __restrict__ out)
{
    const int i = blockIdx.x * blockDim.x + threadIdx.x;  // one float4 per thread
    const float inv = g_inv_sum;
    float4 v = ((float4*)out)[i];
    v.x *= inv; v.y *= inv; v.z *= inv; v.w *= inv;
    ((float4*)out)[i] = v;
}

extern "C" void kernel_launch(void* const* d_in, const int* in_sizes, int n_in,
                              void* d_out, int out_size)
{
    const float* x  = (const float*)d_in[0];
    const float* w1 = (const float*)d_in[1];
    const float* b1 = (const float*)d_in[2];
    const float* w2 = (const float*)d_in[3];
    const float* b2 = (const float*)d_in[4];
    const float* w3 = (const float*)d_in[5];
    const float* b3 = (const float*)d_in[6];
    float* out = (float*)d_out;

    const size_t smem = SM_FLOATS * sizeof(float);
    cudaFuncSetAttribute(mlp_kernel, cudaFuncAttributeMaxDynamicSharedMemorySize, (int)smem);

    mlp_kernel<<<NBLK, TPB, smem>>>(x, w1, b1, w2, b2, w3, b3, out);
    reduce_kernel<<<1, NBLK>>>();
    scale_kernel<<<(B_ROWS * 4) / (4 * 256), 256>>>(out);
}

// round 6
// speedup vs baseline: 2.4003x; 1.0247x over previous
#include <cuda_runtime.h>
#include <cstdint>

// EvroModel: x[131072,256] -> relu(x@w1+b1)[.,64] -> tanh(@w2+b2)[.,16] -> @w3+b3 [.,4]
// -> softmax over the ENTIRE flattened tensor.
//
// Round 6: 3xTF32 mma.sync GEMM with
//  (a) k-permutation so A frags load as float2 (LDG.64), halving LDG instructions
//  (b) B hi/lo frags packed 4-wide in SMEM -> one bank-swizzled LDS.128 per (kt,nt)
//  (c) explicit nt+1 B double-buffer to hide LDS latency.
// Effective k-order (per 8-block): frag row r<4 -> mem col 2r; r>=4 -> 2(r-4)+1.

#define B_ROWS   131072
#define ROWS_CTA 512
#define NBLK     (B_ROWS / ROWS_CTA)   // 256
#define TPB      512
#define KDIM     256
#define H1_PITCH 68

// dynamic smem layout (floats / bytes)
#define SB_OFF_B   0                   // packed B frags: 32768 u32 = 131072 B
#define H1_OFF_F   0                   // ALIAS over sB after GEMM: 512 x 68 floats
#define W2_OFF_F   34816               // 64 x 16
#define B1_OFF_F   35840               // 64
#define B2_OFF_F   35904               // 16
#define W3_OFF_F   35920               // 16 x 4
#define B3_OFF_F   35984               // 4
#define RED_OFF_F  35988               // 512
#define SM_FLOATS  36500

__device__ float g_partials[NBLK];
__device__ float g_inv_sum;

__device__ __forceinline__ uint32_t f2tf32(float v) {
    uint32_t u;
    asm("cvt.rna.tf32.f32 %0, %1;" : "=r"(u) : "f"(v));
    return u;
}
__device__ __forceinline__ uint32_t smem_u32(const void* p) {
    uint32_t a;
    asm("{ .reg .u64 t; cvta.to.shared.u64 t, %1; cvt.u32.u64 %0, t; }" : "=r"(a) : "l"(p));
    return a;
}
__device__ __forceinline__ void lds128(uint32_t r[4], uint32_t addr) {
    asm volatile("ld.shared.v4.b32 {%0,%1,%2,%3}, [%4];"
                 : "=r"(r[0]), "=r"(r[1]), "=r"(r[2]), "=r"(r[3]) : "r"(addr));
}
__device__ __forceinline__ void mma_tf32(float c[4], const uint32_t a[4],
                                         uint32_t b0, uint32_t b1) {
    asm("mma.sync.aligned.m16n8k8.row.col.f32.tf32.tf32.f32 "
        "{%0,%1,%2,%3}, {%4,%5,%6,%7}, {%8,%9}, {%0,%1,%2,%3};"
        : "+f"(c[0]), "+f"(c[1]), "+f"(c[2]), "+f"(c[3])
        : "r"(a[0]), "r"(a[1]), "r"(a[2]), "r"(a[3]), "r"(b0), "r"(b1));
}

__global__ __launch_bounds__(TPB, 1)
void mlp_kernel(const float* __restrict__ x,
                const float* __restrict__ w1, const float* __restrict__ b1,
                const float* __restrict__ w2, const float* __restrict__ b2,
                const float* __restrict__ w3, const float* __restrict__ b3,
                float* __restrict__ out)
{
    extern __shared__ float sm[];
    uint32_t* sB  = (uint32_t*)((char*)sm + SB_OFF_B);
    float*    sh1 = sm + H1_OFF_F;     // aliases sB after the GEMM

    const int tid = threadIdx.x;
    const int wid = tid >> 5;
    const int lane = tid & 31;
    const int g = lane >> 2;       // 0..7
    const int tig = lane & 3;      // 0..3

    // ---- stage w1 as packed tf32 hi/lo B-fragments ----
    // element w1[k][n]: b=k/8, m=k%8 -> t=m>>1, j=m&1 (frag row = t + 4j)
    // store at sB[(((b*8 + nt)*8 + gg)*4 + q)*4 + slot], q=(t+gg)&3,
    // slot: hi -> j, lo -> 2+j
    for (int e = tid; e < 16384; e += TPB) {
        int k = e >> 6, n = e & 63;
        float v = w1[e];
        uint32_t hi = f2tf32(v);
        uint32_t lo = f2tf32(v - __uint_as_float(hi));
        int b = k >> 3, m = k & 7;
        int t = m >> 1, j = m & 1;
        int nt = n >> 3, gg = n & 7;
        int q = (t + gg) & 3;
        uint32_t base = (uint32_t)((((b * 8 + nt) * 8 + gg) * 4 + q) * 4);
        sB[base + j] = hi;
        sB[base + 2 + j] = lo;
    }
    {
        float* sw2 = sm + W2_OFF_F;
        for (int i = tid; i < 1024; i += TPB) sw2[i] = w2[i];
        if (tid < 64) sm[B1_OFF_F + tid] = b1[tid];
        if (tid < 16) sm[B2_OFF_F + tid] = b2[tid];
        if (tid < 64) sm[W3_OFF_F + tid] = w3[tid];
        if (tid < 4)  sm[B3_OFF_F + tid] = b3[tid];
    }
    __syncthreads();

    const uint32_t sB_addr = smem_u32(sB);
    // per-thread constant part of the B address: (g*4 + (tig+g)&3)*16 bytes
    const uint32_t b_lane_off = (uint32_t)((g * 4 + ((tig + g) & 3)) * 16);

    // ---- layer-1 GEMM: warp computes rows [wid*32, wid*32+32), all 64 cols ----
    const float* xb = x + ((size_t)blockIdx.x * ROWS_CTA + wid * 32 + g) * KDIM;

    float c[2][8][4];
    #pragma unroll
    for (int mt = 0; mt < 2; mt++)
        #pragma unroll
        for (int nt = 0; nt < 8; nt++)
            #pragma unroll
            for (int r = 0; r < 4; r++) c[mt][nt][r] = 0.0f;

    // A: float2 at (row, col = kt*8 + 2*tig) gives frag slots (tig, tig+4)
    float2 ra[2][2];   // [mt][row g / row g+8]
    #pragma unroll
    for (int mt = 0; mt < 2; mt++) {
        const float* q = xb + mt * (16 * KDIM) + 2 * tig;
        ra[mt][0] = __ldg((const float2*)q);
        ra[mt][1] = __ldg((const float2*)(q + 8 * KDIM));
    }

    #pragma unroll 1
    for (int kt = 0; kt < 32; kt++) {
        // prefetch next k-tile's A
        float2 rb[2][2];
        if (kt < 31) {
            #pragma unroll
            for (int mt = 0; mt < 2; mt++) {
                const float* q = xb + mt * (16 * KDIM) + (kt + 1) * 8 + 2 * tig;
                rb[mt][0] = __ldg((const float2*)q);
                rb[mt][1] = __ldg((const float2*)(q + 8 * KDIM));
            }
        }

        // split A into tf32 hi/lo (frag order a0..a3)
        uint32_t ah[2][4], al[2][4];
        #pragma unroll
        for (int mt = 0; mt < 2; mt++) {
            float a0 = ra[mt][0].x, a2 = ra[mt][0].y;
            float a1 = ra[mt][1].x, a3 = ra[mt][1].y;
            ah[mt][0] = f2tf32(a0); al[mt][0] = f2tf32(a0 - __uint_as_float(ah[mt][0]));
            ah[mt][1] = f2tf32(a1); al[mt][1] = f2tf32(a1 - __uint_as_float(ah[mt][1]));
            ah[mt][2] = f2tf32(a2); al[mt][2] = f2tf32(a2 - __uint_as_float(ah[mt][2]));
            ah[mt][3] = f2tf32(a3); al[mt][3] = f2tf32(a3 - __uint_as_float(ah[mt][3]));
        }

        // B: one LDS.128 per (kt,nt); double-buffer over nt
        const uint32_t kt_base = sB_addr + (uint32_t)(kt * 8 * 512) + b_lane_off; // nt stride = 8*4*4*4 = 512 B
        uint32_t bc[4], bn[4];
        lds128(bc, kt_base);
        #pragma unroll
        for (int nt = 0; nt < 8; nt++) {
            if (nt < 7) lds128(bn, kt_base + (uint32_t)((nt + 1) * 512));
            #pragma unroll
            for (int mt = 0; mt < 2; mt++) {
                mma_tf32(c[mt][nt], ah[mt], bc[0], bc[1]);   // xh*wh
                mma_tf32(c[mt][nt], ah[mt], bc[2], bc[3]);   // xh*wl
                mma_tf32(c[mt][nt], al[mt], bc[0], bc[1]);   // xl*wh
            }
            #pragma unroll
            for (int s = 0; s < 4; s++) bc[s] = bn[s];
        }

        #pragma unroll
        for (int mt = 0; mt < 2; mt++) {
            ra[mt][0] = rb[mt][0];
            ra[mt][1] = rb[mt][1];
        }
    }

    // ---- sB dead; alias with h1 and write C frags ----
    __syncthreads();
    #pragma unroll
    for (int mt = 0; mt < 2; mt++) {
        int row0 = wid * 32 + mt * 16 + g;
        #pragma unroll
        for (int nt = 0; nt < 8; nt++) {
            int col = nt * 8 + tig * 2;
            float2 v0; v0.x = c[mt][nt][0]; v0.y = c[mt][nt][1];
            float2 v1; v1.x = c[mt][nt][2]; v1.y = c[mt][nt][3];
            *(float2*)&sh1[row0 * H1_PITCH + col] = v0;
            *(float2*)&sh1[(row0 + 8) * H1_PITCH + col] = v1;
        }
    }
    __syncthreads();

    // ---- per-thread fp32 tail: row = tid ----
    const float* sb1 = sm + B1_OFF_F;
    const float* sw2 = sm + W2_OFF_F;
    const float* sb2 = sm + B2_OFF_F;
    const float* sw3 = sm + W3_OFF_F;
    const float* sb3 = sm + B3_OFF_F;
    const float* hrow = &sh1[tid * H1_PITCH];

    float h2[16];
    #pragma unroll
    for (int j = 0; j < 16; j++) h2[j] = sb2[j];
    #pragma unroll
    for (int i4 = 0; i4 < 16; i4++) {
        float4 hv = *(const float4*)&hrow[i4 * 4];
        float h0 = fmaxf(hv.x + sb1[i4 * 4 + 0], 0.0f);
        float h1v = fmaxf(hv.y + sb1[i4 * 4 + 1], 0.0f);
        float h2v = fmaxf(hv.z + sb1[i4 * 4 + 2], 0.0f);
        float h3 = fmaxf(hv.w + sb1[i4 * 4 + 3], 0.0f);
        const float* wr0 = &sw2[(i4 * 4 + 0) * 16];
        const float* wr1 = &sw2[(i4 * 4 + 1) * 16];
        const float* wr2 = &sw2[(i4 * 4 + 2) * 16];
        const float* wr3 = &sw2[(i4 * 4 + 3) * 16];
        #pragma unroll
        for (int j = 0; j < 16; j++) {
            float t = fmaf(h0, wr0[j], h2[j]);
            t = fmaf(h1v, wr1[j], t);
            t = fmaf(h2v, wr2[j], t);
            h2[j] = fmaf(h3, wr3[j], t);
        }
    }
    #pragma unroll
    for (int j = 0; j < 16; j++) h2[j] = tanhf(h2[j]);

    float lg[4];
    #pragma unroll
    for (int j = 0; j < 4; j++) lg[j] = sb3[j];
    #pragma unroll
    for (int i = 0; i < 16; i++) {
        float h = h2[i];
        const float* wr = &sw3[i * 4];
        #pragma unroll
        for (int j = 0; j < 4; j++) lg[j] = fmaf(h, wr[j], lg[j]);
    }

    float e0 = __expf(lg[0]);
    float e1 = __expf(lg[1]);
    float e2 = __expf(lg[2]);
    float e3 = __expf(lg[3]);

    const size_t row = (size_t)blockIdx.x * ROWS_CTA + tid;
    float4 ev; ev.x = e0; ev.y = e1; ev.z = e2; ev.w = e3;
    ((float4*)out)[row] = ev;

    // deterministic block partial sum
    float* red = sm + RED_OFF_F;
    red[tid] = (e0 + e1) + (e2 + e3);
    __syncthreads();
    #pragma unroll
    for (int off = TPB / 2; off > 0; off >>= 1) {
        if (tid < off) red[tid] += red[tid + off];
        __syncthreads();
    }
    if (tid == 0) g_partials[blockIdx.x] = red[0];
}

__global__ void reduce_kernel()
{
    __shared__ float red[NBLK];
    const int tid = threadIdx.x;
    red[tid] = g_partials[tid];
    __syncthreads();
    #pragma unroll
    for (int off = NBLK / 2; off > 0; off >>= 1) {
        if (tid < off) red[tid] += red[tid + off];
        __syncthreads();
    }
    if (tid == 0) g_inv_sum = 1.0f / red[0];
}

__global__ void scale_kernel(float* __restrict__ out)
{
    const int i = blockIdx.x * blockDim.x + threadIdx.x;  // one float4 per thread
    const float inv = g_inv_sum;
    float4 v = ((float4*)out)[i];
    v.x *= inv; v.y *= inv; v.z *= inv; v.w *= inv;
    ((float4*)out)[i] = v;
}

extern "C" void kernel_launch(void* const* d_in, const int* in_sizes, int n_in,
                              void* d_out, int out_size)
{
    const float* x  = (const float*)d_in[0];
    const float* w1 = (const float*)d_in[1];
    const float* b1 = (const float*)d_in[2];
    const float* w2 = (const float*)d_in[3];
    const float* b2 = (const float*)d_in[4];
    const float* w3 = (const float*)d_in[5];
    const float* b3 = (const float*)d_in[6];
    float* out = (float*)d_out;

    const size_t smem = SM_FLOATS * sizeof(float);
    cudaFuncSetAttribute(mlp_kernel, cudaFuncAttributeMaxDynamicSharedMemorySize, (int)smem);

    mlp_kernel<<<NBLK, TPB, smem>>>(x, w1, b1, w2, b2, w3, b3, out);
    reduce_kernel<<<1, NBLK>>>();
    scale_kernel<<<(B_ROWS * 4) / (4 * 256), 256>>>(out);
}